// round 11
// baseline (speedup 1.0000x reference)
#include <cuda_runtime.h>
#include <cuda_fp16.h>
#include <cuda_bf16.h>
#include <cstdint>

#define NN 100000
#define FULL 0xffffffffu
#define CSR_CAP 1900000
#define NB 98           // scan blocks = ceil(NN/1024)

// ---------------- scratch (static __device__, no allocs) ----------------
__device__ __half2 g_h2[NN * 64];    // transformed features [N,128ch] as half2
__device__ float g_s[NN * 4];        // src attention coeff per node/head
__device__ float g_d[NN * 4];        // dst attention coeff per node/head
__device__ float g_f1[NN * 32];      // layer-1 output
__device__ float g_f2[NN * 32];      // layer-2 output
__device__ int   g_deg[NN];          // zero-init at load; re-zeroed by k_scan1 each call
__device__ int   g_start[NN + 1];
__device__ int   g_cursor[NN];
__device__ int   g_csr[CSR_CAP];     // src index per (dst-sorted) edge
__device__ int   g_bsum[NB];

// ---------------- CSR build ----------------
// 4 edges per thread, independent atomic chains
__global__ void k_hist(const int* __restrict__ dst, int E) {
    int i0 = (blockIdx.x * blockDim.x + threadIdx.x) * 4;
    if (i0 + 3 < E) {
        int d0 = dst[i0], d1 = dst[i0 + 1], d2 = dst[i0 + 2], d3 = dst[i0 + 3];
        atomicAdd(&g_deg[d0], 1);
        atomicAdd(&g_deg[d1], 1);
        atomicAdd(&g_deg[d2], 1);
        atomicAdd(&g_deg[d3], 1);
    } else {
        for (int i = i0; i < E; i++) atomicAdd(&g_deg[dst[i]], 1);
    }
}

// per-block exclusive scan of (deg+1); zero deg for next call; block total -> g_bsum
__global__ void k_scan1() {
    __shared__ int wsum[32];
    int t = threadIdx.x, lane = t & 31, wid = t >> 5;
    int i = blockIdx.x * 1024 + t;
    int v = 0;
    if (i < NN) { v = g_deg[i] + 1; g_deg[i] = 0; }
    int incl = v;
    #pragma unroll
    for (int off = 1; off < 32; off <<= 1) {
        int u = __shfl_up_sync(FULL, incl, off);
        if (lane >= off) incl += u;
    }
    if (lane == 31) wsum[wid] = incl;
    __syncthreads();
    if (wid == 0) {
        int wv = wsum[lane];
        int wincl = wv;
        #pragma unroll
        for (int off = 1; off < 32; off <<= 1) {
            int u = __shfl_up_sync(FULL, wincl, off);
            if (lane >= off) wincl += u;
        }
        wsum[lane] = wincl - wv;
    }
    __syncthreads();
    int excl = wsum[wid] + incl - v;
    if (i < NN) g_start[i] = excl;
    if (t == 1023) g_bsum[blockIdx.x] = excl + v;
}

// add block offsets (each block re-scans the 98 partials in smem), init cursor,
// write self-loop edge, write g_start[NN]
__global__ void k_scan3_selfloop() {
    __shared__ int sv[128];
    int t = threadIdx.x;  // 256 threads; first 128 do the partial scan
    if (t < 128) sv[t] = (t < NB) ? g_bsum[t] : 0;
    __syncthreads();
    for (int off = 1; off < 128; off <<= 1) {
        int u = 0;
        if (t < 128 && t >= off) u = sv[t - off];
        __syncthreads();
        if (t < 128) sv[t] += u;
        __syncthreads();
    }
    int i = blockIdx.x * blockDim.x + t;
    if (i < NN) {
        int chunk = i >> 10;
        int boff = (chunk == 0) ? 0 : sv[chunk - 1];
        int p = g_start[i] + boff;
        g_start[i] = p;
        g_cursor[i] = p + 1;
        if (p < CSR_CAP) g_csr[p] = i;
    }
    if (blockIdx.x == 0 && t == 0) g_start[NN] = sv[NB - 1];
}

// 4 edges per thread, independent atomic+store chains
__global__ void k_scatter(const int* __restrict__ src, const int* __restrict__ dst, int E) {
    int i0 = (blockIdx.x * blockDim.x + threadIdx.x) * 4;
    if (i0 + 3 < E) {
        int d0 = dst[i0], d1 = dst[i0 + 1], d2 = dst[i0 + 2], d3 = dst[i0 + 3];
        int s0 = src[i0], s1 = src[i0 + 1], s2 = src[i0 + 2], s3 = src[i0 + 3];
        int p0 = atomicAdd(&g_cursor[d0], 1);
        int p1 = atomicAdd(&g_cursor[d1], 1);
        int p2 = atomicAdd(&g_cursor[d2], 1);
        int p3 = atomicAdd(&g_cursor[d3], 1);
        if (p0 < CSR_CAP) g_csr[p0] = s0;
        if (p1 < CSR_CAP) g_csr[p1] = s1;
        if (p2 < CSR_CAP) g_csr[p2] = s2;
        if (p3 < CSR_CAP) g_csr[p3] = s3;
    } else {
        for (int i = i0; i < E; i++) {
            int pos = atomicAdd(&g_cursor[dst[i]], 1);
            if (pos < CSR_CAP) g_csr[pos] = src[i];
        }
    }
}

// ---------------- transform: h = feat @ W (fp32 math, fp16 store), s/d coeffs fp32 ----------------
template <int K, int LAYER>
__global__ void k_transform(const float* __restrict__ feat_in,
                            const float* __restrict__ W,
                            const float* __restrict__ asrc,
                            const float* __restrict__ adst) {
    const int NPB = 64;
    __shared__ float sW[K * 128];
    __shared__ float sA[256];
    __shared__ float sF[NPB * K];
    const float* feat = (LAYER == 1) ? feat_in : g_f1;
    int t = threadIdx.x;  // 128 threads
    for (int i = t; i < K * 128; i += 128) sW[i] = W[i];
    sA[t]       = asrc[t];
    sA[128 + t] = adst[t];
    int nbase = blockIdx.x * NPB;
    for (int i = t; i < NPB * K; i += 128) {
        long idx = (long)nbase * K + i;
        sF[i] = (idx < (long)NN * K) ? feat[idx] : 0.f;
    }
    __syncthreads();
    int lane = t & 31, hd = t >> 5;
    #pragma unroll 4
    for (int j = 0; j < NPB; j++) {
        int n = nbase + j;
        if (n >= NN) break;
        float acc = 0.f;
        #pragma unroll
        for (int k = 0; k < K; k++) acc = fmaf(sF[j * K + k], sW[k * 128 + t], acc);
        float hi = __shfl_xor_sync(FULL, acc, 1);
        if ((t & 1) == 0) g_h2[n * 64 + (t >> 1)] = __floats2half2_rn(acc, hi);
        float sv = acc * sA[t];
        float dv = acc * sA[128 + t];
        #pragma unroll
        for (int off = 16; off; off >>= 1) {
            sv += __shfl_xor_sync(FULL, sv, off);
            dv += __shfl_xor_sync(FULL, dv, off);
        }
        if (lane == 0) { g_s[n * 4 + hd] = sv; g_d[n * 4 + hd] = dv; }
    }
}

// ---------------- aggregation: paired-edge LDG.128 gathers ----------------
__device__ __forceinline__ void acc8(float* acc, float w, const uint4& u) {
    float2 t0 = __half22float2(*(const __half2*)&u.x);
    float2 t1 = __half22float2(*(const __half2*)&u.y);
    float2 t2 = __half22float2(*(const __half2*)&u.z);
    float2 t3 = __half22float2(*(const __half2*)&u.w);
    acc[0] = fmaf(w, t0.x, acc[0]); acc[1] = fmaf(w, t0.y, acc[1]);
    acc[2] = fmaf(w, t1.x, acc[2]); acc[3] = fmaf(w, t1.y, acc[3]);
    acc[4] = fmaf(w, t2.x, acc[4]); acc[5] = fmaf(w, t2.y, acc[5]);
    acc[6] = fmaf(w, t3.x, acc[6]); acc[7] = fmaf(w, t3.y, acc[7]);
}

template <int LAYER>
__global__ void k_aggregate(const float* __restrict__ bias,
                            const float* __restrict__ Wn,
                            const float* __restrict__ bn,
                            float* __restrict__ nodeout) {
    int n = blockIdx.x * (blockDim.x >> 5) + (threadIdx.x >> 5);
    if (n >= NN) return;
    int lane = threadIdx.x & 31;
    int half = lane >> 4;       // which edge of the pair
    int sub  = lane & 15;       // channel-group owner: channels [8*sub, 8*sub+8)
    int head = sub >> 2;
    int e0 = g_start[n], e1 = g_start[n + 1];
    float dh = g_d[n * 4 + head];

    float acc[8] = {0.f, 0.f, 0.f, 0.f, 0.f, 0.f, 0.f, 0.f};
    float den = 0.f;
    for (int base = e0; base < e1; base += 32) {
        int cnt = min(32, e1 - base);
        int idx = 0;
        if (base + lane < e1) idx = g_csr[base + lane];
        int j = 0;
        for (; j + 3 < cnt; j += 4) {
            int sA = __shfl_sync(FULL, idx, j + half);
            int sB = __shfl_sync(FULL, idx, j + 2 + half);
            float aA = g_s[sA * 4 + head] + dh;
            float aB = g_s[sB * 4 + head] + dh;
            uint4 uA = ((const uint4*)(g_h2 + (size_t)sA * 64))[sub];
            uint4 uB = ((const uint4*)(g_h2 + (size_t)sB * 64))[sub];
            aA = aA > 0.f ? aA : 0.2f * aA;
            aB = aB > 0.f ? aB : 0.2f * aB;
            float wA = __expf(aA), wB = __expf(aB);
            den += wA + wB;
            acc8(acc, wA, uA);
            acc8(acc, wB, uB);
        }
        for (; j < cnt; j += 2) {
            int e = j + half;
            int ec = e < cnt ? e : cnt - 1;
            int s = __shfl_sync(FULL, idx, ec);
            float a = g_s[s * 4 + head] + dh;
            a = a > 0.f ? a : 0.2f * a;
            float w = (e < cnt) ? __expf(a) : 0.f;
            uint4 u = ((const uint4*)(g_h2 + (size_t)s * 64))[sub];
            den += w;
            acc8(acc, w, u);
        }
    }
    den += __shfl_xor_sync(FULL, den, 16);
    #pragma unroll
    for (int i = 0; i < 8; i++) acc[i] += __shfl_xor_sync(FULL, acc[i], 16);
    float inv = 0.25f / den;
    #pragma unroll
    for (int i = 0; i < 8; i++) acc[i] *= inv;
    #pragma unroll
    for (int i = 0; i < 8; i++) {
        acc[i] += __shfl_xor_sync(FULL, acc[i], 4);
        acc[i] += __shfl_xor_sync(FULL, acc[i], 8);
    }
    float o[8];
    if (sub < 4) {
        float4 b0 = ((const float4*)bias)[sub * 2];
        float4 b1 = ((const float4*)bias)[sub * 2 + 1];
        o[0] = fmaxf(acc[0] + b0.x, 0.f);
        o[1] = fmaxf(acc[1] + b0.y, 0.f);
        o[2] = fmaxf(acc[2] + b0.z, 0.f);
        o[3] = fmaxf(acc[3] + b0.w, 0.f);
        o[4] = fmaxf(acc[4] + b1.x, 0.f);
        o[5] = fmaxf(acc[5] + b1.y, 0.f);
        o[6] = fmaxf(acc[6] + b1.z, 0.f);
        o[7] = fmaxf(acc[7] + b1.w, 0.f);
        if (half == 0) {
            float* dstp = (LAYER == 1) ? g_f1 : g_f2;
            float4 w0 = make_float4(o[0], o[1], o[2], o[3]);
            float4 w1 = make_float4(o[4], o[5], o[6], o[7]);
            *(float4*)(dstp + n * 32 + sub * 8)     = w0;
            *(float4*)(dstp + n * 32 + sub * 8 + 4) = w1;
        }
    } else {
        #pragma unroll
        for (int i = 0; i < 8; i++) o[i] = 0.f;
    }
    if (LAYER == 2) {
        float p0 = 0.f, p1 = 0.f;
        if (sub < 4) {
            #pragma unroll
            for (int i = 0; i < 8; i++) {
                int c = sub * 8 + i;
                p0 = fmaf(o[i], __ldg(&Wn[c * 2]),     p0);
                p1 = fmaf(o[i], __ldg(&Wn[c * 2 + 1]), p1);
            }
        }
        p0 += __shfl_xor_sync(FULL, p0, 1);
        p0 += __shfl_xor_sync(FULL, p0, 2);
        p1 += __shfl_xor_sync(FULL, p1, 1);
        p1 += __shfl_xor_sync(FULL, p1, 2);
        if (lane == 0) {
            nodeout[n * 2]     = p0 + bn[0];
            nodeout[n * 2 + 1] = p1 + bn[1];
        }
    }
}

// ---------------- edge MLP via mma.sync m16n8k8 TF32 ----------------
__device__ __forceinline__ unsigned int f2tf32(float f) {
    unsigned int u;
    asm("cvt.rna.tf32.f32 %0, %1;" : "=r"(u) : "f"(f));
    return u;
}

#define SW_STRIDE 72

__global__ void k_edge_mlp_mma(const int* __restrict__ ea,
                               const int* __restrict__ eb, int EL,
                               const float* __restrict__ We1,
                               const float* __restrict__ be1,
                               const float* __restrict__ We2,
                               const float* __restrict__ be2,
                               float* __restrict__ out) {
    __shared__ unsigned int sW[64 * SW_STRIDE];
    __shared__ float sB[64];
    __shared__ float sV[64];
    int t = threadIdx.x;  // 128
    for (int i = t; i < 64 * 64; i += 128) {
        int k = i >> 6, n = i & 63;
        sW[k * SW_STRIDE + n] = f2tf32(We1[i]);
    }
    if (t < 64) { sB[t] = be1[t]; sV[t] = We2[t]; }
    float bb2 = be2[0];
    __syncthreads();

    int lane = t & 31;
    int g = lane >> 2;
    int tg = lane & 3;
    int ntiles = (EL + 15) >> 4;
    int nwarps = gridDim.x * (blockDim.x >> 5);
    int w = blockIdx.x * (blockDim.x >> 5) + (t >> 5);

    for (int tile = w; tile < ntiles; tile += nwarps) {
        int e0 = tile << 4;
        int ra = 0, rb = 0;
        if (lane < 16) {
            int e = e0 + lane;
            if (e < EL) { ra = ea[e]; rb = eb[e]; }
        }
        int iaG  = __shfl_sync(FULL, ra, g);
        int iaG8 = __shfl_sync(FULL, ra, g + 8);
        int ibG  = __shfl_sync(FULL, rb, g);
        int ibG8 = __shfl_sync(FULL, rb, g + 8);
        const float* pA0 = g_f2 + (size_t)iaG  * 32;
        const float* pA1 = g_f2 + (size_t)iaG8 * 32;
        const float* pB0 = g_f2 + (size_t)ibG  * 32;
        const float* pB1 = g_f2 + (size_t)ibG8 * 32;

        unsigned int A0[8], A1[8], A2[8], A3[8];
        #pragma unroll
        for (int kc = 0; kc < 4; kc++) {
            int c = kc * 8 + tg;
            A0[kc] = f2tf32(pA0[c]);
            A1[kc] = f2tf32(pA1[c]);
            A2[kc] = f2tf32(pA0[c + 4]);
            A3[kc] = f2tf32(pA1[c + 4]);
        }
        #pragma unroll
        for (int kc = 4; kc < 8; kc++) {
            int c = (kc - 4) * 8 + tg;
            A0[kc] = f2tf32(pB0[c]);
            A1[kc] = f2tf32(pB1[c]);
            A2[kc] = f2tf32(pB0[c + 4]);
            A3[kc] = f2tf32(pB1[c + 4]);
        }

        float pg = 0.f, pg8 = 0.f;
        #pragma unroll
        for (int nc = 0; nc < 8; nc++) {
            float c0 = 0.f, c1 = 0.f, c2 = 0.f, c3 = 0.f;
            int n0 = nc * 8 + g;
            #pragma unroll
            for (int kc = 0; kc < 8; kc++) {
                unsigned int b0 = sW[(kc * 8 + tg) * SW_STRIDE + n0];
                unsigned int b1 = sW[(kc * 8 + tg + 4) * SW_STRIDE + n0];
                asm volatile(
                    "mma.sync.aligned.m16n8k8.row.col.f32.tf32.tf32.f32 "
                    "{%0,%1,%2,%3},{%4,%5,%6,%7},{%8,%9},{%0,%1,%2,%3};"
                    : "+f"(c0), "+f"(c1), "+f"(c2), "+f"(c3)
                    : "r"(A0[kc]), "r"(A1[kc]), "r"(A2[kc]), "r"(A3[kc]),
                      "r"(b0), "r"(b1));
            }
            int col0 = nc * 8 + 2 * tg;
            float bi0 = sB[col0], bi1 = sB[col0 + 1];
            float v0 = sV[col0],  v1 = sV[col0 + 1];
            pg  = fmaf(fmaxf(c0 + bi0, 0.f), v0, pg);
            pg  = fmaf(fmaxf(c1 + bi1, 0.f), v1, pg);
            pg8 = fmaf(fmaxf(c2 + bi0, 0.f), v0, pg8);
            pg8 = fmaf(fmaxf(c3 + bi1, 0.f), v1, pg8);
        }
        pg  += __shfl_xor_sync(FULL, pg, 1);
        pg  += __shfl_xor_sync(FULL, pg, 2);
        pg8 += __shfl_xor_sync(FULL, pg8, 1);
        pg8 += __shfl_xor_sync(FULL, pg8, 2);
        if (tg == 0) {
            if (e0 + g < EL)     out[e0 + g]     = pg + bb2;
            if (e0 + g + 8 < EL) out[e0 + g + 8] = pg8 + bb2;
        }
    }
}

// ---------------- launch: ONLY kernel launches ----------------
extern "C" void kernel_launch(void* const* d_in, const int* in_sizes, int n_in,
                              void* d_out, int out_size) {
    const float* x    = (const float*)d_in[0];
    const int*   ei   = (const int*)d_in[1];
    const int*   eli  = (const int*)d_in[2];
    const float* W1   = (const float*)d_in[3];
    const float* as1  = (const float*)d_in[4];
    const float* ad1  = (const float*)d_in[5];
    const float* b1   = (const float*)d_in[6];
    const float* W2   = (const float*)d_in[7];
    const float* as2  = (const float*)d_in[8];
    const float* ad2  = (const float*)d_in[9];
    const float* b2   = (const float*)d_in[10];
    const float* Wn   = (const float*)d_in[11];
    const float* bn   = (const float*)d_in[12];
    const float* We1  = (const float*)d_in[13];
    const float* be1  = (const float*)d_in[14];
    const float* We2  = (const float*)d_in[15];
    const float* be2  = (const float*)d_in[16];
    float* out = (float*)d_out;

    int E  = in_sizes[1] / 2;
    int EL = in_sizes[2] / 2;
    const int* src  = ei;
    const int* dst  = ei + E;
    const int* ea   = eli;
    const int* eb   = eli + EL;

    // CSR build
    k_hist<<<(E / 4 + 255) / 256, 256>>>(dst, E);
    k_scan1<<<NB, 1024>>>();
    k_scan3_selfloop<<<(NN + 255) / 256, 256>>>();
    k_scatter<<<(E / 4 + 255) / 256, 256>>>(src, dst, E);

    const int TGRID = (NN + 63) / 64;  // 64 nodes per block
    const int AGRID = (NN + 7) / 8;    // 8 warps per block, 1 node per warp

    // layer 1
    k_transform<9, 1><<<TGRID, 128>>>(x, W1, as1, ad1);
    k_aggregate<1><<<AGRID, 256>>>(b1, nullptr, nullptr, nullptr);
    // layer 2 (+ fused node logits)
    k_transform<32, 2><<<TGRID, 128>>>(nullptr, W2, as2, ad2);
    k_aggregate<2><<<AGRID, 256>>>(b2, Wn, bn, out);

    // edge MLP head
    k_edge_mlp_mma<<<592, 128>>>(ea, eb, EL, We1, be1, We2, be2, out + NN * 2);
}

// round 13
// speedup vs baseline: 1.1076x; 1.1076x over previous
#include <cuda_runtime.h>
#include <cuda_fp16.h>
#include <cuda_bf16.h>
#include <cstdint>

#define NN 100000
#define FULL 0xffffffffu
#define CSR_CAP 1900000
#define NB 98           // scan blocks = ceil(NN/1024)

// ---------------- scratch (static __device__, no allocs) ----------------
__device__ float  g_x32[NN * 16];    // layer-1 input rows, padded to 16 fp32 (64B)
__device__ float  g_s[NN * 4];       // src attention coeff per node/head
__device__ float  g_d[NN * 4];       // dst attention coeff per node/head
__device__ float  g_f1[NN * 32];     // layer-1 output fp32
__device__ __half g_f1h[NN * 32];    // layer-1 output fp16 (for layer-2 gather)
__device__ float  g_f2[NN * 32];     // layer-2 output fp32
__device__ float  g_y1[NN * 64];     // layer-1 weighted input sums (4 heads x 16)
__device__ float  g_y2[NN * 128];    // layer-2 weighted input sums (4 heads x 32)
__device__ int    g_deg[NN];         // zero-init at load; re-zeroed by k_scan1
__device__ int    g_start[NN + 1];
__device__ int    g_cursor[NN];
__device__ int    g_csr[CSR_CAP];
__device__ int    g_bsum[NB];

// ---------------- CSR build (R8-proven) ----------------
__global__ void k_hist(const int* __restrict__ dst, int E) {
    int i = blockIdx.x * blockDim.x + threadIdx.x;
    if (i < E) atomicAdd(&g_deg[dst[i]], 1);
}

__global__ void k_scan1() {
    __shared__ int wsum[32];
    int t = threadIdx.x, lane = t & 31, wid = t >> 5;
    int i = blockIdx.x * 1024 + t;
    int v = 0;
    if (i < NN) { v = g_deg[i] + 1; g_deg[i] = 0; }
    int incl = v;
    #pragma unroll
    for (int off = 1; off < 32; off <<= 1) {
        int u = __shfl_up_sync(FULL, incl, off);
        if (lane >= off) incl += u;
    }
    if (lane == 31) wsum[wid] = incl;
    __syncthreads();
    if (wid == 0) {
        int wv = wsum[lane];
        int wincl = wv;
        #pragma unroll
        for (int off = 1; off < 32; off <<= 1) {
            int u = __shfl_up_sync(FULL, wincl, off);
            if (lane >= off) wincl += u;
        }
        wsum[lane] = wincl - wv;
    }
    __syncthreads();
    int excl = wsum[wid] + incl - v;
    if (i < NN) g_start[i] = excl;
    if (t == 1023) g_bsum[blockIdx.x] = excl + v;
}

__global__ void k_scan3_selfloop() {
    __shared__ int sv[128];
    int t = threadIdx.x;  // 256
    if (t < 128) sv[t] = (t < NB) ? g_bsum[t] : 0;
    __syncthreads();
    for (int off = 1; off < 128; off <<= 1) {
        int u = 0;
        if (t < 128 && t >= off) u = sv[t - off];
        __syncthreads();
        if (t < 128) sv[t] += u;
        __syncthreads();
    }
    int i = blockIdx.x * blockDim.x + t;
    if (i < NN) {
        int chunk = i >> 10;
        int boff = (chunk == 0) ? 0 : sv[chunk - 1];
        int p = g_start[i] + boff;
        g_start[i] = p;
        g_cursor[i] = p + 1;
        if (p < CSR_CAP) g_csr[p] = i;
    }
    if (blockIdx.x == 0 && t == 0) g_start[NN] = sv[NB - 1];
}

__global__ void k_scatter(const int* __restrict__ src, const int* __restrict__ dst, int E) {
    int i = blockIdx.x * blockDim.x + threadIdx.x;
    if (i < E) {
        int pos = atomicAdd(&g_cursor[dst[i]], 1);
        if (pos < CSR_CAP) g_csr[pos] = src[i];
    }
}

// ---------------- prep1: pack x rows, compute s/d via projected attention vectors ----------------
__global__ void k_prep1(const float* __restrict__ x,
                        const float* __restrict__ W1,
                        const float* __restrict__ as1,
                        const float* __restrict__ ad1) {
    __shared__ float swa[9][4], swd[9][4];
    int t = threadIdx.x;  // 256
    if (t < 36) {
        int k = t >> 2, h = t & 3;
        float acc = 0.f;
        for (int j = 0; j < 32; j++) acc = fmaf(W1[k * 128 + h * 32 + j], as1[h * 32 + j], acc);
        swa[k][h] = acc;
    } else if (t >= 64 && t < 100) {
        int tt = t - 64;
        int k = tt >> 2, h = tt & 3;
        float acc = 0.f;
        for (int j = 0; j < 32; j++) acc = fmaf(W1[k * 128 + h * 32 + j], ad1[h * 32 + j], acc);
        swd[k][h] = acc;
    }
    __syncthreads();
    int n = blockIdx.x * blockDim.x + t;
    if (n >= NN) return;
    float xv[9];
    #pragma unroll
    for (int k = 0; k < 9; k++) xv[k] = x[n * 9 + k];
    #pragma unroll
    for (int h = 0; h < 4; h++) {
        float s = 0.f, d = 0.f;
        #pragma unroll
        for (int k = 0; k < 9; k++) {
            s = fmaf(xv[k], swa[k][h], s);
            d = fmaf(xv[k], swd[k][h], d);
        }
        g_s[n * 4 + h] = s;
        g_d[n * 4 + h] = d;
    }
    float4* xr = (float4*)(g_x32 + (size_t)n * 16);
    xr[0] = make_float4(xv[0], xv[1], xv[2], xv[3]);
    xr[1] = make_float4(xv[4], xv[5], xv[6], xv[7]);
    xr[2] = make_float4(xv[8], 0.f, 0.f, 0.f);
    xr[3] = make_float4(0.f, 0.f, 0.f, 0.f);
}

// ---------------- agg1: warp/node; lane = (head, ch-pair); gather 64B fp32 x rows ----------------
// Every lane walks ALL edges (channel-parallel) -> den is complete per-lane; NO cross-lane reduce.
__global__ void k_agg1() {
    int n = blockIdx.x * (blockDim.x >> 5) + (threadIdx.x >> 5);
    if (n >= NN) return;
    int lane = threadIdx.x & 31;
    int h = lane >> 3, cp = lane & 7;
    int e0 = g_start[n], e1 = g_start[n + 1];
    float dh = g_d[n * 4 + h];
    float y0 = 0.f, y1 = 0.f, den = 0.f;
    for (int base = e0; base < e1; base += 32) {
        int cnt = min(32, e1 - base);
        int idx = 0;
        if (base + lane < e1) idx = g_csr[base + lane];
        int j = 0;
        for (; j + 1 < cnt; j += 2) {
            int s0 = __shfl_sync(FULL, idx, j);
            int s1 = __shfl_sync(FULL, idx, j + 1);
            float aa = g_s[s0 * 4 + h] + dh;
            float ab = g_s[s1 * 4 + h] + dh;
            float2 v0 = *(const float2*)(g_x32 + (size_t)s0 * 16 + cp * 2);
            float2 v1 = *(const float2*)(g_x32 + (size_t)s1 * 16 + cp * 2);
            aa = aa > 0.f ? aa : 0.2f * aa;
            ab = ab > 0.f ? ab : 0.2f * ab;
            float w0 = __expf(aa), w1 = __expf(ab);
            den += w0 + w1;
            y0 = fmaf(w0, v0.x, y0); y1 = fmaf(w0, v0.y, y1);
            y0 = fmaf(w1, v1.x, y0); y1 = fmaf(w1, v1.y, y1);
        }
        if (j < cnt) {
            int s0 = __shfl_sync(FULL, idx, j);
            float aa = g_s[s0 * 4 + h] + dh;
            float2 v0 = *(const float2*)(g_x32 + (size_t)s0 * 16 + cp * 2);
            aa = aa > 0.f ? aa : 0.2f * aa;
            float w0 = __expf(aa);
            den += w0;
            y0 = fmaf(w0, v0.x, y0); y1 = fmaf(w0, v0.y, y1);
        }
    }
    float inv = 0.25f / den;   // den already complete per-lane
    *(float2*)(g_y1 + (size_t)n * 64 + h * 16 + cp * 2) = make_float2(y0 * inv, y1 * inv);
}

// ---------------- prep2: s2/d2 from f1, write f1 as fp16 ----------------
__global__ void k_prep2(const float* __restrict__ W2,
                        const float* __restrict__ as2,
                        const float* __restrict__ ad2) {
    __shared__ float swa[32][4], swd[32][4];
    int t = threadIdx.x;  // 256
    if (t < 128) {
        int k = t >> 2, h = t & 3;
        float a = 0.f, d = 0.f;
        for (int j = 0; j < 32; j++) {
            float w = W2[k * 128 + h * 32 + j];
            a = fmaf(w, as2[h * 32 + j], a);
            d = fmaf(w, ad2[h * 32 + j], d);
        }
        swa[k][h] = a;
        swd[k][h] = d;
    }
    __syncthreads();
    int n = blockIdx.x * blockDim.x + t;
    if (n >= NN) return;
    float f[32];
    const float4* fr = (const float4*)(g_f1 + (size_t)n * 32);
    #pragma unroll
    for (int i = 0; i < 8; i++) {
        float4 v = fr[i];
        f[i * 4] = v.x; f[i * 4 + 1] = v.y; f[i * 4 + 2] = v.z; f[i * 4 + 3] = v.w;
    }
    #pragma unroll
    for (int h = 0; h < 4; h++) {
        float s = 0.f, d = 0.f;
        #pragma unroll
        for (int k = 0; k < 32; k++) {
            s = fmaf(f[k], swa[k][h], s);
            d = fmaf(f[k], swd[k][h], d);
        }
        g_s[n * 4 + h] = s;
        g_d[n * 4 + h] = d;
    }
    __half2* hr = (__half2*)(g_f1h + (size_t)n * 32);
    #pragma unroll
    for (int i = 0; i < 16; i++) hr[i] = __floats2half2_rn(f[2 * i], f[2 * i + 1]);
}

// ---------------- agg2: warp/node; lane = (head, ch-quad); gather 64B fp16 f1 rows ----------------
__global__ void k_agg2() {
    int n = blockIdx.x * (blockDim.x >> 5) + (threadIdx.x >> 5);
    if (n >= NN) return;
    int lane = threadIdx.x & 31;
    int h = lane >> 3, q = lane & 7;
    int e0 = g_start[n], e1 = g_start[n + 1];
    float dh = g_d[n * 4 + h];
    float c0 = 0.f, c1 = 0.f, c2 = 0.f, c3 = 0.f, den = 0.f;
    for (int base = e0; base < e1; base += 32) {
        int cnt = min(32, e1 - base);
        int idx = 0;
        if (base + lane < e1) idx = g_csr[base + lane];
        int j = 0;
        for (; j + 1 < cnt; j += 2) {
            int s0 = __shfl_sync(FULL, idx, j);
            int s1 = __shfl_sync(FULL, idx, j + 1);
            float aa = g_s[s0 * 4 + h] + dh;
            float ab = g_s[s1 * 4 + h] + dh;
            uint2 u0 = *(const uint2*)(g_f1h + (size_t)s0 * 32 + q * 4);
            uint2 u1 = *(const uint2*)(g_f1h + (size_t)s1 * 32 + q * 4);
            aa = aa > 0.f ? aa : 0.2f * aa;
            ab = ab > 0.f ? ab : 0.2f * ab;
            float w0 = __expf(aa), w1 = __expf(ab);
            den += w0 + w1;
            float2 p0 = __half22float2(*(__half2*)&u0.x);
            float2 r0 = __half22float2(*(__half2*)&u0.y);
            float2 p1 = __half22float2(*(__half2*)&u1.x);
            float2 r1 = __half22float2(*(__half2*)&u1.y);
            c0 = fmaf(w0, p0.x, c0); c1 = fmaf(w0, p0.y, c1);
            c2 = fmaf(w0, r0.x, c2); c3 = fmaf(w0, r0.y, c3);
            c0 = fmaf(w1, p1.x, c0); c1 = fmaf(w1, p1.y, c1);
            c2 = fmaf(w1, r1.x, c2); c3 = fmaf(w1, r1.y, c3);
        }
        if (j < cnt) {
            int s0 = __shfl_sync(FULL, idx, j);
            float aa = g_s[s0 * 4 + h] + dh;
            uint2 u0 = *(const uint2*)(g_f1h + (size_t)s0 * 32 + q * 4);
            aa = aa > 0.f ? aa : 0.2f * aa;
            float w0 = __expf(aa);
            den += w0;
            float2 p0 = __half22float2(*(__half2*)&u0.x);
            float2 r0 = __half22float2(*(__half2*)&u0.y);
            c0 = fmaf(w0, p0.x, c0); c1 = fmaf(w0, p0.y, c1);
            c2 = fmaf(w0, r0.x, c2); c3 = fmaf(w0, r0.y, c3);
        }
    }
    float inv = 0.25f / den;   // den already complete per-lane
    *(float4*)(g_y2 + (size_t)n * 128 + h * 32 + q * 4) =
        make_float4(c0 * inv, c1 * inv, c2 * inv, c3 * inv);
}

// ---------------- epilogue GEMM via mma.sync m16n8k8 TF32 ----------------
// f = relu(y' @ Wstack + bias); LAYER==2 also fuses node logits.
__device__ __forceinline__ unsigned int f2tf32(float f) {
    unsigned int u;
    asm("cvt.rna.tf32.f32 %0, %1;" : "=r"(u) : "f"(f));
    return u;
}

template <int K, int LAYER>
__global__ void k_epi(const float* __restrict__ Wsrc,
                      const float* __restrict__ bias,
                      const float* __restrict__ Wn,
                      const float* __restrict__ bn,
                      float* __restrict__ nodeout) {
    const int S = 36;
    const int KH = K / 4;
    const int K0 = (LAYER == 1) ? 9 : 32;
    __shared__ unsigned int sW[K * S];
    __shared__ float sB[32];
    int t = threadIdx.x;  // 128
    for (int i = t; i < K * 32; i += 128) {
        int k = i >> 5, n = i & 31;
        int h = k / KH, kk = k % KH;
        float v = (kk < K0) ? Wsrc[kk * 128 + h * 32 + n] : 0.f;
        sW[k * S + n] = f2tf32(v);
    }
    if (t < 32) sB[t] = bias[t];
    __syncthreads();
    int lane = t & 31;
    int g = lane >> 2, tg = lane & 3;
    int ntiles = (NN + 15) >> 4;
    int tile = blockIdx.x * (blockDim.x >> 5) + (t >> 5);
    if (tile >= ntiles) return;
    int r0 = tile << 4;
    int rowA = r0 + g, rowB = r0 + g + 8;   // NN % 16 == 0, always in range
    const float* Y = (LAYER == 1) ? g_y1 : g_y2;
    const float* pA = Y + (size_t)rowA * K;
    const float* pB = Y + (size_t)rowB * K;
    unsigned int A0[K / 8], A1[K / 8], A2[K / 8], A3[K / 8];
    #pragma unroll
    for (int kc = 0; kc < K / 8; kc++) {
        int c = kc * 8 + tg;
        A0[kc] = f2tf32(pA[c]);
        A1[kc] = f2tf32(pB[c]);
        A2[kc] = f2tf32(pA[c + 4]);
        A3[kc] = f2tf32(pB[c + 4]);
    }
    float* fout = (LAYER == 1) ? g_f1 : g_f2;
    float p0 = 0.f, p1 = 0.f, q0 = 0.f, q1 = 0.f;
    #pragma unroll
    for (int nc = 0; nc < 4; nc++) {
        float c0 = 0.f, c1 = 0.f, c2 = 0.f, c3 = 0.f;
        int n0 = nc * 8 + g;
        #pragma unroll
        for (int kc = 0; kc < K / 8; kc++) {
            unsigned int b0 = sW[(kc * 8 + tg) * S + n0];
            unsigned int b1 = sW[(kc * 8 + tg + 4) * S + n0];
            asm volatile(
                "mma.sync.aligned.m16n8k8.row.col.f32.tf32.tf32.f32 "
                "{%0,%1,%2,%3},{%4,%5,%6,%7},{%8,%9},{%0,%1,%2,%3};"
                : "+f"(c0), "+f"(c1), "+f"(c2), "+f"(c3)
                : "r"(A0[kc]), "r"(A1[kc]), "r"(A2[kc]), "r"(A3[kc]),
                  "r"(b0), "r"(b1));
        }
        int col0 = nc * 8 + 2 * tg;
        float o0 = fmaxf(c0 + sB[col0],     0.f);
        float o1 = fmaxf(c1 + sB[col0 + 1], 0.f);
        float o2 = fmaxf(c2 + sB[col0],     0.f);
        float o3 = fmaxf(c3 + sB[col0 + 1], 0.f);
        fout[(size_t)rowA * 32 + col0]     = o0;
        fout[(size_t)rowA * 32 + col0 + 1] = o1;
        fout[(size_t)rowB * 32 + col0]     = o2;
        fout[(size_t)rowB * 32 + col0 + 1] = o3;
        if (LAYER == 2) {
            p0 = fmaf(o0, __ldg(&Wn[col0 * 2]),           p0);
            p1 = fmaf(o0, __ldg(&Wn[col0 * 2 + 1]),       p1);
            p0 = fmaf(o1, __ldg(&Wn[(col0 + 1) * 2]),     p0);
            p1 = fmaf(o1, __ldg(&Wn[(col0 + 1) * 2 + 1]), p1);
            q0 = fmaf(o2, __ldg(&Wn[col0 * 2]),           q0);
            q1 = fmaf(o2, __ldg(&Wn[col0 * 2 + 1]),       q1);
            q0 = fmaf(o3, __ldg(&Wn[(col0 + 1) * 2]),     q0);
            q1 = fmaf(o3, __ldg(&Wn[(col0 + 1) * 2 + 1]), q1);
        }
    }
    if (LAYER == 2) {
        p0 += __shfl_xor_sync(FULL, p0, 1); p0 += __shfl_xor_sync(FULL, p0, 2);
        p1 += __shfl_xor_sync(FULL, p1, 1); p1 += __shfl_xor_sync(FULL, p1, 2);
        q0 += __shfl_xor_sync(FULL, q0, 1); q0 += __shfl_xor_sync(FULL, q0, 2);
        q1 += __shfl_xor_sync(FULL, q1, 1); q1 += __shfl_xor_sync(FULL, q1, 2);
        if (tg == 0) {
            nodeout[rowA * 2]     = p0 + bn[0];
            nodeout[rowA * 2 + 1] = p1 + bn[1];
            nodeout[rowB * 2]     = q0 + bn[0];
            nodeout[rowB * 2 + 1] = q1 + bn[1];
        }
    }
}

// ---------------- edge MLP via mma.sync m16n8k8 TF32 (unchanged, proven) ----------------
#define SW_STRIDE 72

__global__ void k_edge_mlp_mma(const int* __restrict__ ea,
                               const int* __restrict__ eb, int EL,
                               const float* __restrict__ We1,
                               const float* __restrict__ be1,
                               const float* __restrict__ We2,
                               const float* __restrict__ be2,
                               float* __restrict__ out) {
    __shared__ unsigned int sW[64 * SW_STRIDE];
    __shared__ float sB[64];
    __shared__ float sV[64];
    int t = threadIdx.x;  // 128
    for (int i = t; i < 64 * 64; i += 128) {
        int k = i >> 6, n = i & 63;
        sW[k * SW_STRIDE + n] = f2tf32(We1[i]);
    }
    if (t < 64) { sB[t] = be1[t]; sV[t] = We2[t]; }
    float bb2 = be2[0];
    __syncthreads();

    int lane = t & 31;
    int g = lane >> 2;
    int tg = lane & 3;
    int ntiles = (EL + 15) >> 4;
    int nwarps = gridDim.x * (blockDim.x >> 5);
    int w = blockIdx.x * (blockDim.x >> 5) + (t >> 5);

    for (int tile = w; tile < ntiles; tile += nwarps) {
        int e0 = tile << 4;
        int ra = 0, rb = 0;
        if (lane < 16) {
            int e = e0 + lane;
            if (e < EL) { ra = ea[e]; rb = eb[e]; }
        }
        int iaG  = __shfl_sync(FULL, ra, g);
        int iaG8 = __shfl_sync(FULL, ra, g + 8);
        int ibG  = __shfl_sync(FULL, rb, g);
        int ibG8 = __shfl_sync(FULL, rb, g + 8);
        const float* pA0 = g_f2 + (size_t)iaG  * 32;
        const float* pA1 = g_f2 + (size_t)iaG8 * 32;
        const float* pB0 = g_f2 + (size_t)ibG  * 32;
        const float* pB1 = g_f2 + (size_t)ibG8 * 32;

        unsigned int A0[8], A1[8], A2[8], A3[8];
        #pragma unroll
        for (int kc = 0; kc < 4; kc++) {
            int c = kc * 8 + tg;
            A0[kc] = f2tf32(pA0[c]);
            A1[kc] = f2tf32(pA1[c]);
            A2[kc] = f2tf32(pA0[c + 4]);
            A3[kc] = f2tf32(pA1[c + 4]);
        }
        #pragma unroll
        for (int kc = 4; kc < 8; kc++) {
            int c = (kc - 4) * 8 + tg;
            A0[kc] = f2tf32(pB0[c]);
            A1[kc] = f2tf32(pB1[c]);
            A2[kc] = f2tf32(pB0[c + 4]);
            A3[kc] = f2tf32(pB1[c + 4]);
        }

        float pg = 0.f, pg8 = 0.f;
        #pragma unroll
        for (int nc = 0; nc < 8; nc++) {
            float c0 = 0.f, c1 = 0.f, c2 = 0.f, c3 = 0.f;
            int n0 = nc * 8 + g;
            #pragma unroll
            for (int kc = 0; kc < 8; kc++) {
                unsigned int b0 = sW[(kc * 8 + tg) * SW_STRIDE + n0];
                unsigned int b1 = sW[(kc * 8 + tg + 4) * SW_STRIDE + n0];
                asm volatile(
                    "mma.sync.aligned.m16n8k8.row.col.f32.tf32.tf32.f32 "
                    "{%0,%1,%2,%3},{%4,%5,%6,%7},{%8,%9},{%0,%1,%2,%3};"
                    : "+f"(c0), "+f"(c1), "+f"(c2), "+f"(c3)
                    : "r"(A0[kc]), "r"(A1[kc]), "r"(A2[kc]), "r"(A3[kc]),
                      "r"(b0), "r"(b1));
            }
            int col0 = nc * 8 + 2 * tg;
            float bi0 = sB[col0], bi1 = sB[col0 + 1];
            float v0 = sV[col0],  v1 = sV[col0 + 1];
            pg  = fmaf(fmaxf(c0 + bi0, 0.f), v0, pg);
            pg  = fmaf(fmaxf(c1 + bi1, 0.f), v1, pg);
            pg8 = fmaf(fmaxf(c2 + bi0, 0.f), v0, pg8);
            pg8 = fmaf(fmaxf(c3 + bi1, 0.f), v1, pg8);
        }
        pg  += __shfl_xor_sync(FULL, pg, 1);
        pg  += __shfl_xor_sync(FULL, pg, 2);
        pg8 += __shfl_xor_sync(FULL, pg8, 1);
        pg8 += __shfl_xor_sync(FULL, pg8, 2);
        if (tg == 0) {
            if (e0 + g < EL)     out[e0 + g]     = pg + bb2;
            if (e0 + g + 8 < EL) out[e0 + g + 8] = pg8 + bb2;
        }
    }
}

// ---------------- launch: ONLY kernel launches ----------------
extern "C" void kernel_launch(void* const* d_in, const int* in_sizes, int n_in,
                              void* d_out, int out_size) {
    const float* x    = (const float*)d_in[0];
    const int*   ei   = (const int*)d_in[1];
    const int*   eli  = (const int*)d_in[2];
    const float* W1   = (const float*)d_in[3];
    const float* as1  = (const float*)d_in[4];
    const float* ad1  = (const float*)d_in[5];
    const float* b1   = (const float*)d_in[6];
    const float* W2   = (const float*)d_in[7];
    const float* as2  = (const float*)d_in[8];
    const float* ad2  = (const float*)d_in[9];
    const float* b2   = (const float*)d_in[10];
    const float* Wn   = (const float*)d_in[11];
    const float* bn   = (const float*)d_in[12];
    const float* We1  = (const float*)d_in[13];
    const float* be1  = (const float*)d_in[14];
    const float* We2  = (const float*)d_in[15];
    const float* be2  = (const float*)d_in[16];
    float* out = (float*)d_out;

    int E  = in_sizes[1] / 2;
    int EL = in_sizes[2] / 2;
    const int* src  = ei;
    const int* dst  = ei + E;
    const int* ea   = eli;
    const int* eb   = eli + EL;

    // CSR build
    k_hist<<<(E + 255) / 256, 256>>>(dst, E);
    k_scan1<<<NB, 1024>>>();
    k_scan3_selfloop<<<(NN + 255) / 256, 256>>>();
    k_scatter<<<(E + 255) / 256, 256>>>(src, dst, E);

    const int AGRID = (NN + 7) / 8;          // warp per node
    const int EPIGRID = ((NN + 15) / 16 + 3) / 4;  // 4 warp-tiles per block

    // layer 1
    k_prep1<<<(NN + 255) / 256, 256>>>(x, W1, as1, ad1);
    k_agg1<<<AGRID, 256>>>();
    k_epi<64, 1><<<EPIGRID, 128>>>(W1, b1, nullptr, nullptr, nullptr);
    // layer 2
    k_prep2<<<(NN + 255) / 256, 256>>>(W2, as2, ad2);
    k_agg2<<<AGRID, 256>>>();
    k_epi<128, 2><<<EPIGRID, 128>>>(W2, b2, Wn, bn, out);

    // edge MLP head
    k_edge_mlp_mma<<<592, 128>>>(ea, eb, EL, We1, be1, We2, be2, out + NN * 2);
}